// round 1
// baseline (speedup 1.0000x reference)
#include <cuda_runtime.h>
#include <cuda_bf16.h>

// Problem constants (fixed shapes from the reference):
//   N=1, C=2, H=64, W=64, D=32, radius=(3,3,1), SIGMA_XY=5, SIGMA_IMG=0.1, WEIGHT=1
#define NH 64
#define NW 64
#define ND 32
#define NL (NH * NW * ND)   // 131072

// Scratch: packed (sample, y0) per voxel; global double accumulator.
__device__ double g_acc;
__device__ float2 g_sy[NL];

__global__ void k_init() { g_acc = 0.0; }

__global__ void k_pack(const float* __restrict__ y, const float* __restrict__ s) {
    int p = blockIdx.x * blockDim.x + threadIdx.x;
    if (p < NL) g_sy[p] = make_float2(s[p], y[p]);
}

__global__ __launch_bounds__(256) void k_main(const float* __restrict__ spacing) {
    const int p = blockIdx.x * blockDim.x + threadIdx.x;
    const int d = p & (ND - 1);
    const int w = (p >> 5) & (NW - 1);
    const int h = p >> 11;

    const float2 c0 = g_sy[p];
    const float sp  = c0.x;
    const float y0p = c0.y;
    const float m   = 1.0f - 2.0f * y0p;   // 1-dot = fmaf(y0q, m, y0p)

    const float sH = __ldg(spacing + 0);
    const float sW = __ldg(spacing + 1);
    const float sD = __ldg(spacing + 2);
    // exponent spatial coeffs: -0.5*(s*delta/5)^2 = -(s^2/50)*delta^2
    const float aH = sH * sH * (1.0f / 50.0f);
    const float aW = sW * sW * (1.0f / 50.0f);
    const float aD = sD * sD * (1.0f / 50.0f);

    float acc = 0.0f;

    // Half-space offset enumeration (73 of the 146 non-center taps);
    // each in-bounds pair counted once, doubled below (k and (1-dot) are symmetric).
    #pragma unroll
    for (int dz = 0; dz <= 1; ++dz) {
        #pragma unroll
        for (int dw = -3; dw <= 3; ++dw) {
            #pragma unroll
            for (int dh = -3; dh <= 3; ++dh) {
                if (dz == 0 && (dw < 0 || (dw == 0 && dh <= 0))) continue;
                const int hh = h + dh;
                const int ww = w + dw;
                const int zz = d + dz;
                if (((unsigned)hh < NH) & ((unsigned)ww < NW) & ((unsigned)zz < ND)) {
                    const float2 cq = g_sy[p + dh * (NW * ND) + dw * ND + dz];
                    const float ds   = sp - cq.x;
                    const float coff = -(aH * (float)(dh * dh)
                                       + aW * (float)(dw * dw)
                                       + aD * (float)(dz * dz));
                    // img exponent: -0.5*(ds/0.1)^2 = -50*ds^2
                    const float expo = fmaf(-50.0f * ds, ds, coff);
                    const float k = __expf(expo);
                    const float t = fmaf(cq.y, m, y0p);   // 1 - sum_c y_c(p) y_c(q)
                    acc = fmaf(k, t, acc);
                }
            }
        }
    }
    acc *= 2.0f;

    // Out-of-bounds taps: patch value is 0 (zero-padded unfold), so
    // k_oob(p) = exp(-0.5*||f(p)||^2), identical for every OOB offset;
    // y contribution is 0. Count OOB offsets analytically.
    const int cntH = min(h, 3) + min(NH - 1 - h, 3) + 1;
    const int cntW = min(w, 3) + min(NW - 1 - w, 3) + 1;
    const int cntD = min(d, 1) + min(ND - 1 - d, 1) + 1;
    const int noob = 147 - cntH * cntW * cntD;
    if (noob) {
        const float e = -(aH * (float)(h * h) + aW * (float)(w * w) + aD * (float)(d * d))
                        - 50.0f * sp * sp;
        acc = fmaf((float)noob, __expf(e), acc);
    }

    // Reduction: warp shuffle -> shared -> one double atomic per block.
    #pragma unroll
    for (int o = 16; o; o >>= 1) acc += __shfl_down_sync(0xffffffffu, acc, o);
    __shared__ float warp_s[8];
    const int lane = threadIdx.x & 31;
    const int wid  = threadIdx.x >> 5;
    if (lane == 0) warp_s[wid] = acc;
    __syncthreads();
    if (wid == 0) {
        float v = (lane < 8) ? warp_s[lane] : 0.0f;
        #pragma unroll
        for (int o = 4; o; o >>= 1) v += __shfl_down_sync(0xffffffffu, v, o);
        if (lane == 0) atomicAdd(&g_acc, (double)v);
    }
}

__global__ void k_fin(float* out) {
    out[0] = (float)(g_acc * (1.0 / (double)NL));
}

extern "C" void kernel_launch(void* const* d_in, const int* in_sizes, int n_in,
                              void* d_out, int out_size) {
    const float* y       = (const float*)d_in[0];  // (1,2,64,64,32) softmax
    const float* sample  = (const float*)d_in[1];  // (1,1,64,64,32)
    const float* spacing = (const float*)d_in[2];  // (3,1)
    float* out = (float*)d_out;

    k_init<<<1, 1>>>();
    k_pack<<<NL / 256, 256>>>(y, sample);
    k_main<<<NL / 256, 256>>>(spacing);
    k_fin<<<1, 1>>>(out);
}